// round 15
// baseline (speedup 1.0000x reference)
#include <cuda_runtime.h>
#include <cuda_fp16.h>
#include <cstdint>

#define N_NODES 100000
#define N_EDGES 600000
#define IN_C    128
#define OUT_C   128
#define M_TILE  128
#define N_TILES ((N_NODES + M_TILE - 1) / M_TILE)   // 782
#define M_PAD   (N_TILES * M_TILE)                  // 100096

#define AH_STRIDE 136
#define BH_STRIDE 136
#define A_BYTES   (M_TILE * AH_STRIDE * 2)           // 34816
#define B_BYTES   (IN_C  * BH_STRIDE * 2)            // 34816
#define SMEM_BYTES (A_BYTES + B_BYTES)               // 69632

#define NB      N_NODES                               // dst-only buckets
#define SCAN_BS 2048
#define SCAN_BLOCKS ((NB + SCAN_BS - 1) / SCAN_BS)   // 49

// h[r][M_PAD][128] in fp16 (flat row id = rel*M_PAD + src)
__device__ __half2 g_hh[(size_t)3 * M_PAD * (OUT_C / 2)];
// CSR (g_cnt zeroed at load; re-zeroed by scan_c every run)
__device__ int g_cnt[NB];
__device__ int g_rowstart[NB + 1];
__device__ int g_cursor[NB];
__device__ int g_sorted[3 * N_EDGES];                // packed h-row ids
__device__ int g_partial[SCAN_BLOCKS];

// ---------------------------------------------------------------------------
// 1) GEMM: h_j = x @ W_j via mma.sync.m16n8k16.f16 + ldmatrix (unchanged)
// ---------------------------------------------------------------------------
__global__ __launch_bounds__(256, 2) void gemm_hmma_kernel(
        const float4* __restrict__ x4,
        const float* __restrict__ W0,
        const float* __restrict__ W1,
        const float* __restrict__ W2) {
    extern __shared__ char smem[];
    char* As = smem;
    char* Bs = smem + A_BYTES;

    int tid  = threadIdx.x;
    int lane = tid & 31;
    int wid  = tid >> 5;
    int wr   = wid >> 2;
    int wc   = wid & 3;
    int g    = lane >> 2;
    int tg   = lane & 3;

    int tile_row0 = blockIdx.x * M_TILE;

    uint32_t As_u = (uint32_t)__cvta_generic_to_shared(As);
    uint32_t Bs_u = (uint32_t)__cvta_generic_to_shared(Bs);

    #pragma unroll
    for (int i = tid; i < 4096; i += 256) {
        int row = i >> 5, c4 = i & 31;
        int srow = tile_row0 + row;
        if (srow >= N_NODES) srow = 0;
        float4 v = __ldg(x4 + (size_t)srow * (IN_C / 4) + c4);
        __half2 h0 = __floats2half2_rn(v.x, v.y);
        __half2 h1 = __floats2half2_rn(v.z, v.w);
        uint2 u = { *reinterpret_cast<uint32_t*>(&h0),
                    *reinterpret_cast<uint32_t*>(&h1) };
        *reinterpret_cast<uint2*>(As + row * (AH_STRIDE * 2) + c4 * 8) = u;
    }

    for (int rel = 0; rel < 3; rel++) {
        const float* Wj = (rel == 0) ? W0 : (rel == 1 ? W1 : W2);
        __half2* hj = g_hh + (size_t)rel * M_PAD * (OUT_C / 2);

        __syncthreads();
        #pragma unroll
        for (int i = tid; i < 4096; i += 256) {
            int k = i >> 5, n4 = i & 31;
            float4 v = __ldg(reinterpret_cast<const float4*>(
                             Wj + (size_t)k * OUT_C) + n4);
            __half2 h0 = __floats2half2_rn(v.x, v.y);
            __half2 h1 = __floats2half2_rn(v.z, v.w);
            uint2 u = { *reinterpret_cast<uint32_t*>(&h0),
                        *reinterpret_cast<uint32_t*>(&h1) };
            *reinterpret_cast<uint2*>(Bs + k * (BH_STRIDE * 2) + n4 * 8) = u;
        }
        __syncthreads();

        float acc[4][4][4];
        #pragma unroll
        for (int mt = 0; mt < 4; mt++)
            #pragma unroll
            for (int nt = 0; nt < 4; nt++)
                #pragma unroll
                for (int r = 0; r < 4; r++) acc[mt][nt][r] = 0.f;

        #pragma unroll
        for (int ks = 0; ks < IN_C / 16; ks++) {
            uint32_t a[4][4], b[4][2];
            #pragma unroll
            for (int mt = 0; mt < 4; mt++) {
                int arow = wr * 64 + mt * 16 + (lane & 15);
                uint32_t addr = As_u + arow * (AH_STRIDE * 2)
                              + ks * 32 + ((lane >> 4) * 16);
                asm volatile(
                    "ldmatrix.sync.aligned.m8n8.x4.shared.b16 {%0,%1,%2,%3}, [%4];"
                    : "=r"(a[mt][0]), "=r"(a[mt][1]),
                      "=r"(a[mt][2]), "=r"(a[mt][3])
                    : "r"(addr));
            }
            #pragma unroll
            for (int nt = 0; nt < 4; nt++) {
                int brow = ks * 16 + (lane & 15);
                uint32_t addr = Bs_u + brow * (BH_STRIDE * 2)
                              + (wc * 32 + nt * 8) * 2;
                asm volatile(
                    "ldmatrix.sync.aligned.m8n8.x2.trans.shared.b16 {%0,%1}, [%2];"
                    : "=r"(b[nt][0]), "=r"(b[nt][1])
                    : "r"(addr));
            }
            #pragma unroll
            for (int mt = 0; mt < 4; mt++)
                #pragma unroll
                for (int nt = 0; nt < 4; nt++) {
                    asm volatile(
                        "mma.sync.aligned.m16n8k16.row.col.f32.f16.f16.f32 "
                        "{%0,%1,%2,%3}, {%4,%5,%6,%7}, {%8,%9}, {%0,%1,%2,%3};"
                        : "+f"(acc[mt][nt][0]), "+f"(acc[mt][nt][1]),
                          "+f"(acc[mt][nt][2]), "+f"(acc[mt][nt][3])
                        : "r"(a[mt][0]), "r"(a[mt][1]),
                          "r"(a[mt][2]), "r"(a[mt][3]),
                          "r"(b[nt][0]), "r"(b[nt][1]));
                }
        }

        #pragma unroll
        for (int mt = 0; mt < 4; mt++) {
            int row = tile_row0 + wr * 64 + mt * 16 + g;
            #pragma unroll
            for (int nt = 0; nt < 4; nt++) {
                int col = wc * 32 + nt * 8 + 2 * tg;
                hj[(size_t)row * (OUT_C / 2) + col / 2] =
                    __floats2half2_rn(acc[mt][nt][0], acc[mt][nt][1]);
                hj[(size_t)(row + 8) * (OUT_C / 2) + col / 2] =
                    __floats2half2_rn(acc[mt][nt][2], acc[mt][nt][3]);
            }
        }
    }
}

// ---------------------------------------------------------------------------
// CSR build (dst-only buckets): count (x16) -> scan_a -> scan_c -> fill (x16)
// ---------------------------------------------------------------------------
#define E16 (N_EDGES / 16)   // 37500

__global__ void count_kernel(const int* __restrict__ d0,
                             const int* __restrict__ d1,
                             const int* __restrict__ d2) {
    unsigned gid = blockIdx.x * blockDim.x + threadIdx.x;
    if (gid >= 3u * E16) return;
    int rel = gid / E16;
    int e16 = gid % E16;
    const int* dp = (rel == 0) ? d0 : (rel == 1 ? d1 : d2);
    int4 d[4];
    #pragma unroll
    for (int q = 0; q < 4; q++)
        d[q] = __ldg(reinterpret_cast<const int4*>(dp) + e16 * 4 + q);
    #pragma unroll
    for (int q = 0; q < 4; q++) {
        atomicAdd(g_cnt + d[q].x, 1); atomicAdd(g_cnt + d[q].y, 1);
        atomicAdd(g_cnt + d[q].z, 1); atomicAdd(g_cnt + d[q].w, 1);
    }
}

__global__ void scan_a_kernel() {
    __shared__ int sb[256];
    int t = threadIdx.x;
    int base = blockIdx.x * SCAN_BS + t * 8;
    int sum = 0;
    #pragma unroll
    for (int j = 0; j < 8; j++) {
        int idx = base + j;
        if (idx < NB) sum += g_cnt[idx];
    }
    sb[t] = sum;
    __syncthreads();
    for (int off = 128; off > 0; off >>= 1) {
        if (t < off) sb[t] += sb[t + off];
        __syncthreads();
    }
    if (t == 0) g_partial[blockIdx.x] = sb[0];
}

__global__ void scan_c_kernel() {
    __shared__ int sb[256];
    __shared__ int base_sh;
    int t = threadIdx.x;

    int p = (t < (int)blockIdx.x && t < SCAN_BLOCKS) ? g_partial[t] : 0;
    sb[t] = p;
    __syncthreads();
    for (int off = 128; off > 0; off >>= 1) {
        if (t < off) sb[t] += sb[t + off];
        __syncthreads();
    }
    if (t == 0) base_sh = sb[0];
    __syncthreads();

    int base = blockIdx.x * SCAN_BS + t * 8;
    int v[8];
    int tsum = 0;
    #pragma unroll
    for (int j = 0; j < 8; j++) {
        int idx = base + j;
        v[j] = (idx < NB) ? g_cnt[idx] : 0;
        if (idx < NB) g_cnt[idx] = 0;          // re-zero for next run
        tsum += v[j];
    }
    sb[t] = tsum;
    __syncthreads();
    for (int off = 1; off < 256; off <<= 1) {
        int add = (t >= off) ? sb[t - off] : 0;
        __syncthreads();
        sb[t] += add;
        __syncthreads();
    }
    int run = base_sh + sb[t] - tsum;
    #pragma unroll
    for (int j = 0; j < 8; j++) {
        int idx = base + j;
        if (idx < NB) {
            g_rowstart[idx] = run;
            g_cursor[idx] = run;
            run += v[j];
        }
    }
    if (blockIdx.x == 0 && t == 0) g_rowstart[NB] = 3 * N_EDGES;
}

__global__ void fill_kernel(const int* __restrict__ s0, const int* __restrict__ d0,
                            const int* __restrict__ s1, const int* __restrict__ d1,
                            const int* __restrict__ s2, const int* __restrict__ d2) {
    unsigned gid = blockIdx.x * blockDim.x + threadIdx.x;
    if (gid >= 3u * E16) return;
    int rel = gid / E16;
    int e16 = gid % E16;
    const int* sp = (rel == 0) ? s0 : (rel == 1 ? s1 : s2);
    const int* dp = (rel == 0) ? d0 : (rel == 1 ? d1 : d2);
    int4 s[4], d[4];
    #pragma unroll
    for (int q = 0; q < 4; q++) {
        s[q] = __ldg(reinterpret_cast<const int4*>(sp) + e16 * 4 + q);
        d[q] = __ldg(reinterpret_cast<const int4*>(dp) + e16 * 4 + q);
    }
    int rbase = rel * M_PAD;
    // 16 independent atomicAdd round trips in flight (MLP 16)
    int pos[16];
    #pragma unroll
    for (int q = 0; q < 4; q++) {
        pos[q * 4 + 0] = atomicAdd(g_cursor + d[q].x, 1);
        pos[q * 4 + 1] = atomicAdd(g_cursor + d[q].y, 1);
        pos[q * 4 + 2] = atomicAdd(g_cursor + d[q].z, 1);
        pos[q * 4 + 3] = atomicAdd(g_cursor + d[q].w, 1);
    }
    #pragma unroll
    for (int q = 0; q < 4; q++) {
        g_sorted[pos[q * 4 + 0]] = rbase + s[q].x;
        g_sorted[pos[q * 4 + 1]] = rbase + s[q].y;
        g_sorted[pos[q * 4 + 2]] = rbase + s[q].z;
        g_sorted[pos[q * 4 + 3]] = rbase + s[q].w;
    }
}

// ---------------------------------------------------------------------------
// Gather: one warp per node, one segment. Index broadcast: one coalesced LDG
// loads 32 indices (lane -> shfl), row loads issue in 16-wide groups (MLP 16).
// ---------------------------------------------------------------------------
static __device__ __forceinline__ void accum_u2(float4& acc, uint2 u) {
    float2 f0 = __half22float2(*reinterpret_cast<__half2*>(&u.x));
    float2 f1 = __half22float2(*reinterpret_cast<__half2*>(&u.y));
    acc.x += f0.x; acc.y += f0.y; acc.z += f1.x; acc.w += f1.y;
}

__global__ void gather_kernel(float4* __restrict__ out4) {
    unsigned n    = (blockIdx.x * blockDim.x + threadIdx.x) >> 5;
    int      lane = threadIdx.x & 31;
    if (n >= (unsigned)N_NODES) return;

    int e   = __ldg(&g_rowstart[n]);
    int end = __ldg(&g_rowstart[n + 1]);

    const char* hb = reinterpret_cast<const char*>(g_hh);
    float4 acc = make_float4(0.f, 0.f, 0.f, 0.f);

    for (int blk = e; blk < end; blk += 32) {
        int cnt = end - blk;
        if (cnt > 32) cnt = 32;
        int myidx = 0;
        if (blk + lane < end) myidx = __ldg(&g_sorted[blk + lane]);

        int j = 0;
        for (; j + 16 <= cnt; j += 16) {
            uint2 u[16];
            #pragma unroll
            for (int k = 0; k < 16; k++) {
                int r = __shfl_sync(0xffffffffu, myidx, j + k);
                u[k] = __ldg(reinterpret_cast<const uint2*>(
                             hb + (size_t)r * 256 + lane * 8));
            }
            #pragma unroll
            for (int k = 0; k < 16; k++) accum_u2(acc, u[k]);
        }
        if (j + 8 <= cnt) {
            uint2 u[8];
            #pragma unroll
            for (int k = 0; k < 8; k++) {
                int r = __shfl_sync(0xffffffffu, myidx, j + k);
                u[k] = __ldg(reinterpret_cast<const uint2*>(
                             hb + (size_t)r * 256 + lane * 8));
            }
            #pragma unroll
            for (int k = 0; k < 8; k++) accum_u2(acc, u[k]);
            j += 8;
        }
        if (j + 4 <= cnt) {
            uint2 u[4];
            #pragma unroll
            for (int k = 0; k < 4; k++) {
                int r = __shfl_sync(0xffffffffu, myidx, j + k);
                u[k] = __ldg(reinterpret_cast<const uint2*>(
                             hb + (size_t)r * 256 + lane * 8));
            }
            #pragma unroll
            for (int k = 0; k < 4; k++) accum_u2(acc, u[k]);
            j += 4;
        }
        for (; j < cnt; j++) {
            int r = __shfl_sync(0xffffffffu, myidx, j);
            uint2 u = __ldg(reinterpret_cast<const uint2*>(
                            hb + (size_t)r * 256 + lane * 8));
            accum_u2(acc, u);
        }
    }

    acc.x = fmaxf(acc.x, 0.f); acc.y = fmaxf(acc.y, 0.f);
    acc.z = fmaxf(acc.z, 0.f); acc.w = fmaxf(acc.w, 0.f);
    out4[(size_t)n * (OUT_C / 4) + lane] = acc;
}

// ---------------------------------------------------------------------------
// launch: CSR on side stream || GEMM on main stream, join, gather.
// ---------------------------------------------------------------------------
extern "C" void kernel_launch(void* const* d_in, const int* in_sizes, int n_in,
                              void* d_out, int out_size) {
    const float* x  = (const float*)d_in[0];
    const float* W0 = (const float*)d_in[1];
    const float* W1 = (const float*)d_in[2];
    const float* W2 = (const float*)d_in[3];
    const int* s0 = (const int*)d_in[4];
    const int* d0 = (const int*)d_in[5];
    const int* s1 = (const int*)d_in[6];
    const int* d1 = (const int*)d_in[7];
    const int* s2 = (const int*)d_in[8];
    const int* d2 = (const int*)d_in[9];
    float* out = (float*)d_out;

    static cudaStream_t s_side = nullptr;
    static cudaEvent_t  ev_fork = nullptr, ev_join = nullptr;
    static bool init_done = false;
    if (!init_done) {
        cudaStreamCreateWithFlags(&s_side, cudaStreamNonBlocking);
        cudaEventCreateWithFlags(&ev_fork, cudaEventDisableTiming);
        cudaEventCreateWithFlags(&ev_join, cudaEventDisableTiming);
        cudaFuncSetAttribute(gemm_hmma_kernel,
                             cudaFuncAttributeMaxDynamicSharedMemorySize,
                             SMEM_BYTES);
        init_done = true;
    }

    cudaEventRecord(ev_fork, 0);
    cudaStreamWaitEvent(s_side, ev_fork, 0);

    count_kernel<<<(3 * E16 + 255) / 256, 256, 0, s_side>>>(d0, d1, d2);
    scan_a_kernel<<<SCAN_BLOCKS, 256, 0, s_side>>>();
    scan_c_kernel<<<SCAN_BLOCKS, 256, 0, s_side>>>();
    fill_kernel<<<(3 * E16 + 255) / 256, 256, 0, s_side>>>(s0, d0, s1, d1, s2, d2);
    cudaEventRecord(ev_join, s_side);

    gemm_hmma_kernel<<<N_TILES, 256, SMEM_BYTES>>>(
        reinterpret_cast<const float4*>(x), W0, W1, W2);

    cudaStreamWaitEvent(0, ev_join, 0);
    {
        long long threads = (long long)N_NODES * 32;
        int blocks = (int)((threads + 255) / 256);
        gather_kernel<<<blocks, 256>>>(reinterpret_cast<float4*>(out));
    }
}

// round 16
// speedup vs baseline: 1.1717x; 1.1717x over previous
#include <cuda_runtime.h>
#include <cuda_fp16.h>
#include <cstdint>

#define N_NODES 100000
#define N_EDGES 600000
#define IN_C    128
#define OUT_C   128
#define M_TILE  128
#define N_TILES ((N_NODES + M_TILE - 1) / M_TILE)   // 782
#define M_PAD   (N_TILES * M_TILE)                  // 100096

#define AH_STRIDE 136
#define BH_STRIDE 136
#define A_BYTES   (M_TILE * AH_STRIDE * 2)           // 34816
#define B_BYTES   (IN_C  * BH_STRIDE * 2)            // 34816
#define SMEM_BYTES (A_BYTES + B_BYTES)               // 69632

#define NB      N_NODES                               // dst-only buckets
#define SCAN_BS 2048
#define SCAN_BLOCKS ((NB + SCAN_BS - 1) / SCAN_BS)   // 49

// h[r][M_PAD][128] in fp16 (flat row id = rel*M_PAD + src)
__device__ __half2 g_hh[(size_t)3 * M_PAD * (OUT_C / 2)];
// CSR (g_cnt zeroed at load; re-zeroed by scan_c every run)
__device__ int g_cnt[NB];
__device__ int g_rowstart[NB + 1];
__device__ int g_cursor[NB];
__device__ int g_sorted[3 * N_EDGES];                // packed h-row ids
__device__ int g_partial[SCAN_BLOCKS];

// ---------------------------------------------------------------------------
// 1) GEMM: h_j = x @ W_j via mma.sync.m16n8k16.f16 + ldmatrix (unchanged)
// ---------------------------------------------------------------------------
__global__ __launch_bounds__(256, 2) void gemm_hmma_kernel(
        const float4* __restrict__ x4,
        const float* __restrict__ W0,
        const float* __restrict__ W1,
        const float* __restrict__ W2) {
    extern __shared__ char smem[];
    char* As = smem;
    char* Bs = smem + A_BYTES;

    int tid  = threadIdx.x;
    int lane = tid & 31;
    int wid  = tid >> 5;
    int wr   = wid >> 2;
    int wc   = wid & 3;
    int g    = lane >> 2;
    int tg   = lane & 3;

    int tile_row0 = blockIdx.x * M_TILE;

    uint32_t As_u = (uint32_t)__cvta_generic_to_shared(As);
    uint32_t Bs_u = (uint32_t)__cvta_generic_to_shared(Bs);

    #pragma unroll
    for (int i = tid; i < 4096; i += 256) {
        int row = i >> 5, c4 = i & 31;
        int srow = tile_row0 + row;
        if (srow >= N_NODES) srow = 0;
        float4 v = __ldg(x4 + (size_t)srow * (IN_C / 4) + c4);
        __half2 h0 = __floats2half2_rn(v.x, v.y);
        __half2 h1 = __floats2half2_rn(v.z, v.w);
        uint2 u = { *reinterpret_cast<uint32_t*>(&h0),
                    *reinterpret_cast<uint32_t*>(&h1) };
        *reinterpret_cast<uint2*>(As + row * (AH_STRIDE * 2) + c4 * 8) = u;
    }

    for (int rel = 0; rel < 3; rel++) {
        const float* Wj = (rel == 0) ? W0 : (rel == 1 ? W1 : W2);
        __half2* hj = g_hh + (size_t)rel * M_PAD * (OUT_C / 2);

        __syncthreads();
        #pragma unroll
        for (int i = tid; i < 4096; i += 256) {
            int k = i >> 5, n4 = i & 31;
            float4 v = __ldg(reinterpret_cast<const float4*>(
                             Wj + (size_t)k * OUT_C) + n4);
            __half2 h0 = __floats2half2_rn(v.x, v.y);
            __half2 h1 = __floats2half2_rn(v.z, v.w);
            uint2 u = { *reinterpret_cast<uint32_t*>(&h0),
                        *reinterpret_cast<uint32_t*>(&h1) };
            *reinterpret_cast<uint2*>(Bs + k * (BH_STRIDE * 2) + n4 * 8) = u;
        }
        __syncthreads();

        float acc[4][4][4];
        #pragma unroll
        for (int mt = 0; mt < 4; mt++)
            #pragma unroll
            for (int nt = 0; nt < 4; nt++)
                #pragma unroll
                for (int r = 0; r < 4; r++) acc[mt][nt][r] = 0.f;

        #pragma unroll
        for (int ks = 0; ks < IN_C / 16; ks++) {
            uint32_t a[4][4], b[4][2];
            #pragma unroll
            for (int mt = 0; mt < 4; mt++) {
                int arow = wr * 64 + mt * 16 + (lane & 15);
                uint32_t addr = As_u + arow * (AH_STRIDE * 2)
                              + ks * 32 + ((lane >> 4) * 16);
                asm volatile(
                    "ldmatrix.sync.aligned.m8n8.x4.shared.b16 {%0,%1,%2,%3}, [%4];"
                    : "=r"(a[mt][0]), "=r"(a[mt][1]),
                      "=r"(a[mt][2]), "=r"(a[mt][3])
                    : "r"(addr));
            }
            #pragma unroll
            for (int nt = 0; nt < 4; nt++) {
                int brow = ks * 16 + (lane & 15);
                uint32_t addr = Bs_u + brow * (BH_STRIDE * 2)
                              + (wc * 32 + nt * 8) * 2;
                asm volatile(
                    "ldmatrix.sync.aligned.m8n8.x2.trans.shared.b16 {%0,%1}, [%2];"
                    : "=r"(b[nt][0]), "=r"(b[nt][1])
                    : "r"(addr));
            }
            #pragma unroll
            for (int mt = 0; mt < 4; mt++)
                #pragma unroll
                for (int nt = 0; nt < 4; nt++) {
                    asm volatile(
                        "mma.sync.aligned.m16n8k16.row.col.f32.f16.f16.f32 "
                        "{%0,%1,%2,%3}, {%4,%5,%6,%7}, {%8,%9}, {%0,%1,%2,%3};"
                        : "+f"(acc[mt][nt][0]), "+f"(acc[mt][nt][1]),
                          "+f"(acc[mt][nt][2]), "+f"(acc[mt][nt][3])
                        : "r"(a[mt][0]), "r"(a[mt][1]),
                          "r"(a[mt][2]), "r"(a[mt][3]),
                          "r"(b[nt][0]), "r"(b[nt][1]));
                }
        }

        #pragma unroll
        for (int mt = 0; mt < 4; mt++) {
            int row = tile_row0 + wr * 64 + mt * 16 + g;
            #pragma unroll
            for (int nt = 0; nt < 4; nt++) {
                int col = wc * 32 + nt * 8 + 2 * tg;
                hj[(size_t)row * (OUT_C / 2) + col / 2] =
                    __floats2half2_rn(acc[mt][nt][0], acc[mt][nt][1]);
                hj[(size_t)(row + 8) * (OUT_C / 2) + col / 2] =
                    __floats2half2_rn(acc[mt][nt][2], acc[mt][nt][3]);
            }
        }
    }
}

// ---------------------------------------------------------------------------
// CSR build (dst-only buckets): count (x4) -> scan_a -> scan_c -> fill (x4)
// x4 = measured optimum (R12 fill 25.4us; x8/x16 regress via occupancy loss)
// ---------------------------------------------------------------------------
#define E4 (N_EDGES / 4)   // 150000

__global__ void count_kernel(const int* __restrict__ d0,
                             const int* __restrict__ d1,
                             const int* __restrict__ d2) {
    unsigned gid = blockIdx.x * blockDim.x + threadIdx.x;
    if (gid >= 3u * E4) return;
    int rel = gid / E4;
    int e4  = gid % E4;
    const int* dp = (rel == 0) ? d0 : (rel == 1 ? d1 : d2);
    int4 d = __ldg(reinterpret_cast<const int4*>(dp) + e4);
    atomicAdd(g_cnt + d.x, 1); atomicAdd(g_cnt + d.y, 1);
    atomicAdd(g_cnt + d.z, 1); atomicAdd(g_cnt + d.w, 1);
}

__global__ void scan_a_kernel() {
    __shared__ int sb[256];
    int t = threadIdx.x;
    int base = blockIdx.x * SCAN_BS + t * 8;
    int sum = 0;
    #pragma unroll
    for (int j = 0; j < 8; j++) {
        int idx = base + j;
        if (idx < NB) sum += g_cnt[idx];
    }
    sb[t] = sum;
    __syncthreads();
    for (int off = 128; off > 0; off >>= 1) {
        if (t < off) sb[t] += sb[t + off];
        __syncthreads();
    }
    if (t == 0) g_partial[blockIdx.x] = sb[0];
}

__global__ void scan_c_kernel() {
    __shared__ int sb[256];
    __shared__ int base_sh;
    int t = threadIdx.x;

    int p = (t < (int)blockIdx.x && t < SCAN_BLOCKS) ? g_partial[t] : 0;
    sb[t] = p;
    __syncthreads();
    for (int off = 128; off > 0; off >>= 1) {
        if (t < off) sb[t] += sb[t + off];
        __syncthreads();
    }
    if (t == 0) base_sh = sb[0];
    __syncthreads();

    int base = blockIdx.x * SCAN_BS + t * 8;
    int v[8];
    int tsum = 0;
    #pragma unroll
    for (int j = 0; j < 8; j++) {
        int idx = base + j;
        v[j] = (idx < NB) ? g_cnt[idx] : 0;
        if (idx < NB) g_cnt[idx] = 0;          // re-zero for next run
        tsum += v[j];
    }
    sb[t] = tsum;
    __syncthreads();
    for (int off = 1; off < 256; off <<= 1) {
        int add = (t >= off) ? sb[t - off] : 0;
        __syncthreads();
        sb[t] += add;
        __syncthreads();
    }
    int run = base_sh + sb[t] - tsum;
    #pragma unroll
    for (int j = 0; j < 8; j++) {
        int idx = base + j;
        if (idx < NB) {
            g_rowstart[idx] = run;
            g_cursor[idx] = run;
            run += v[j];
        }
    }
    if (blockIdx.x == 0 && t == 0) g_rowstart[NB] = 3 * N_EDGES;
}

__global__ void fill_kernel(const int* __restrict__ s0, const int* __restrict__ d0,
                            const int* __restrict__ s1, const int* __restrict__ d1,
                            const int* __restrict__ s2, const int* __restrict__ d2) {
    unsigned gid = blockIdx.x * blockDim.x + threadIdx.x;
    if (gid >= 3u * E4) return;
    int rel = gid / E4;
    int e4  = gid % E4;
    const int* sp = (rel == 0) ? s0 : (rel == 1 ? s1 : s2);
    const int* dp = (rel == 0) ? d0 : (rel == 1 ? d1 : d2);
    int4 s = __ldg(reinterpret_cast<const int4*>(sp) + e4);
    int4 d = __ldg(reinterpret_cast<const int4*>(dp) + e4);
    int rbase = rel * M_PAD;
    g_sorted[atomicAdd(g_cursor + d.x, 1)] = rbase + s.x;
    g_sorted[atomicAdd(g_cursor + d.y, 1)] = rbase + s.y;
    g_sorted[atomicAdd(g_cursor + d.z, 1)] = rbase + s.z;
    g_sorted[atomicAdd(g_cursor + d.w, 1)] = rbase + s.w;
}

// ---------------------------------------------------------------------------
// Gather: one warp per node, one flat segment, 8-wide unroll (R14 version).
// ---------------------------------------------------------------------------
__global__ void gather_kernel(float4* __restrict__ out4) {
    unsigned n    = (blockIdx.x * blockDim.x + threadIdx.x) >> 5;
    int      lane = threadIdx.x & 31;
    if (n >= (unsigned)N_NODES) return;

    int e   = __ldg(&g_rowstart[n]);
    int end = __ldg(&g_rowstart[n + 1]);

    const char* hb = reinterpret_cast<const char*>(g_hh);
    float4 acc = make_float4(0.f, 0.f, 0.f, 0.f);

    for (; e + 7 < end; e += 8) {
        int r[8];
        #pragma unroll
        for (int j = 0; j < 8; j++) r[j] = __ldg(&g_sorted[e + j]);
        uint2 u[8];
        #pragma unroll
        for (int j = 0; j < 8; j++)
            u[j] = __ldg(reinterpret_cast<const uint2*>(
                         hb + (size_t)r[j] * 256 + lane * 8));
        #pragma unroll
        for (int j = 0; j < 8; j++) {
            float2 f0 = __half22float2(*reinterpret_cast<__half2*>(&u[j].x));
            float2 f1 = __half22float2(*reinterpret_cast<__half2*>(&u[j].y));
            acc.x += f0.x; acc.y += f0.y; acc.z += f1.x; acc.w += f1.y;
        }
    }
    for (; e + 1 < end; e += 2) {
        int r0 = __ldg(&g_sorted[e]);
        int r1 = __ldg(&g_sorted[e + 1]);
        uint2 u0 = __ldg(reinterpret_cast<const uint2*>(hb + (size_t)r0 * 256 + lane * 8));
        uint2 u1 = __ldg(reinterpret_cast<const uint2*>(hb + (size_t)r1 * 256 + lane * 8));
        float2 a0 = __half22float2(*reinterpret_cast<__half2*>(&u0.x));
        float2 a1 = __half22float2(*reinterpret_cast<__half2*>(&u0.y));
        float2 b0 = __half22float2(*reinterpret_cast<__half2*>(&u1.x));
        float2 b1 = __half22float2(*reinterpret_cast<__half2*>(&u1.y));
        acc.x += a0.x + b0.x; acc.y += a0.y + b0.y;
        acc.z += a1.x + b1.x; acc.w += a1.y + b1.y;
    }
    if (e < end) {
        int r0 = __ldg(&g_sorted[e]);
        uint2 u = __ldg(reinterpret_cast<const uint2*>(hb + (size_t)r0 * 256 + lane * 8));
        float2 f0 = __half22float2(*reinterpret_cast<__half2*>(&u.x));
        float2 f1 = __half22float2(*reinterpret_cast<__half2*>(&u.y));
        acc.x += f0.x; acc.y += f0.y; acc.z += f1.x; acc.w += f1.y;
    }

    acc.x = fmaxf(acc.x, 0.f); acc.y = fmaxf(acc.y, 0.f);
    acc.z = fmaxf(acc.z, 0.f); acc.w = fmaxf(acc.w, 0.f);
    out4[(size_t)n * (OUT_C / 4) + lane] = acc;
}

// ---------------------------------------------------------------------------
// launch: CSR on side stream || GEMM on main stream, join, gather.
// ---------------------------------------------------------------------------
extern "C" void kernel_launch(void* const* d_in, const int* in_sizes, int n_in,
                              void* d_out, int out_size) {
    const float* x  = (const float*)d_in[0];
    const float* W0 = (const float*)d_in[1];
    const float* W1 = (const float*)d_in[2];
    const float* W2 = (const float*)d_in[3];
    const int* s0 = (const int*)d_in[4];
    const int* d0 = (const int*)d_in[5];
    const int* s1 = (const int*)d_in[6];
    const int* d1 = (const int*)d_in[7];
    const int* s2 = (const int*)d_in[8];
    const int* d2 = (const int*)d_in[9];
    float* out = (float*)d_out;

    static cudaStream_t s_side = nullptr;
    static cudaEvent_t  ev_fork = nullptr, ev_join = nullptr;
    static bool init_done = false;
    if (!init_done) {
        cudaStreamCreateWithFlags(&s_side, cudaStreamNonBlocking);
        cudaEventCreateWithFlags(&ev_fork, cudaEventDisableTiming);
        cudaEventCreateWithFlags(&ev_join, cudaEventDisableTiming);
        cudaFuncSetAttribute(gemm_hmma_kernel,
                             cudaFuncAttributeMaxDynamicSharedMemorySize,
                             SMEM_BYTES);
        init_done = true;
    }

    cudaEventRecord(ev_fork, 0);
    cudaStreamWaitEvent(s_side, ev_fork, 0);

    count_kernel<<<(3 * E4 + 255) / 256, 256, 0, s_side>>>(d0, d1, d2);
    scan_a_kernel<<<SCAN_BLOCKS, 256, 0, s_side>>>();
    scan_c_kernel<<<SCAN_BLOCKS, 256, 0, s_side>>>();
    fill_kernel<<<(3 * E4 + 255) / 256, 256, 0, s_side>>>(s0, d0, s1, d1, s2, d2);
    cudaEventRecord(ev_join, s_side);

    gemm_hmma_kernel<<<N_TILES, 256, SMEM_BYTES>>>(
        reinterpret_cast<const float4*>(x), W0, W1, W2);

    cudaStreamWaitEvent(0, ev_join, 0);
    {
        long long threads = (long long)N_NODES * 32;
        int blocks = (int)((threads + 255) / 256);
        gather_kernel<<<blocks, 256>>>(reinterpret_cast<float4*>(out));
    }
}

// round 17
// speedup vs baseline: 1.1841x; 1.0106x over previous
#include <cuda_runtime.h>
#include <cuda_fp16.h>
#include <cstdint>

#define N_NODES 100000
#define N_EDGES 600000
#define IN_C    128
#define OUT_C   128
#define M_TILE  128
#define N_TILES ((N_NODES + M_TILE - 1) / M_TILE)   // 782
#define M_PAD   (N_TILES * M_TILE)                  // 100096

#define AH_STRIDE 136
#define BH_STRIDE 136
#define A_BYTES   (M_TILE * AH_STRIDE * 2)           // 34816
#define B_BYTES   (IN_C  * BH_STRIDE * 2)            // 34816
#define SMEM_BYTES (A_BYTES + B_BYTES)               // 69632

#define NB      N_NODES                               // dst-only buckets
#define SCAN_BS 2048
#define SCAN_BLOCKS ((NB + SCAN_BS - 1) / SCAN_BS)   // 49

// h[r][M_PAD][128] in fp16 (flat row id = rel*M_PAD + src)
__device__ __half2 g_hh[(size_t)3 * M_PAD * (OUT_C / 2)];
// CSR (g_cnt zeroed at load; re-zeroed by scan_c every run)
__device__ int g_cnt[NB];
__device__ int g_rowstart[NB + 1];
__device__ int g_rank[3 * N_EDGES];                  // within-bucket rank per edge
__device__ int g_sorted[3 * N_EDGES];                // packed h-row ids
__device__ int g_partial[SCAN_BLOCKS];

// ---------------------------------------------------------------------------
// 1) GEMM: h_j = x @ W_j via mma.sync.m16n8k16.f16 + ldmatrix (unchanged)
// ---------------------------------------------------------------------------
__global__ __launch_bounds__(256, 2) void gemm_hmma_kernel(
        const float4* __restrict__ x4,
        const float* __restrict__ W0,
        const float* __restrict__ W1,
        const float* __restrict__ W2) {
    extern __shared__ char smem[];
    char* As = smem;
    char* Bs = smem + A_BYTES;

    int tid  = threadIdx.x;
    int lane = tid & 31;
    int wid  = tid >> 5;
    int wr   = wid >> 2;
    int wc   = wid & 3;
    int g    = lane >> 2;
    int tg   = lane & 3;

    int tile_row0 = blockIdx.x * M_TILE;

    uint32_t As_u = (uint32_t)__cvta_generic_to_shared(As);
    uint32_t Bs_u = (uint32_t)__cvta_generic_to_shared(Bs);

    #pragma unroll
    for (int i = tid; i < 4096; i += 256) {
        int row = i >> 5, c4 = i & 31;
        int srow = tile_row0 + row;
        if (srow >= N_NODES) srow = 0;
        float4 v = __ldg(x4 + (size_t)srow * (IN_C / 4) + c4);
        __half2 h0 = __floats2half2_rn(v.x, v.y);
        __half2 h1 = __floats2half2_rn(v.z, v.w);
        uint2 u = { *reinterpret_cast<uint32_t*>(&h0),
                    *reinterpret_cast<uint32_t*>(&h1) };
        *reinterpret_cast<uint2*>(As + row * (AH_STRIDE * 2) + c4 * 8) = u;
    }

    for (int rel = 0; rel < 3; rel++) {
        const float* Wj = (rel == 0) ? W0 : (rel == 1 ? W1 : W2);
        __half2* hj = g_hh + (size_t)rel * M_PAD * (OUT_C / 2);

        __syncthreads();
        #pragma unroll
        for (int i = tid; i < 4096; i += 256) {
            int k = i >> 5, n4 = i & 31;
            float4 v = __ldg(reinterpret_cast<const float4*>(
                             Wj + (size_t)k * OUT_C) + n4);
            __half2 h0 = __floats2half2_rn(v.x, v.y);
            __half2 h1 = __floats2half2_rn(v.z, v.w);
            uint2 u = { *reinterpret_cast<uint32_t*>(&h0),
                        *reinterpret_cast<uint32_t*>(&h1) };
            *reinterpret_cast<uint2*>(Bs + k * (BH_STRIDE * 2) + n4 * 8) = u;
        }
        __syncthreads();

        float acc[4][4][4];
        #pragma unroll
        for (int mt = 0; mt < 4; mt++)
            #pragma unroll
            for (int nt = 0; nt < 4; nt++)
                #pragma unroll
                for (int r = 0; r < 4; r++) acc[mt][nt][r] = 0.f;

        #pragma unroll
        for (int ks = 0; ks < IN_C / 16; ks++) {
            uint32_t a[4][4], b[4][2];
            #pragma unroll
            for (int mt = 0; mt < 4; mt++) {
                int arow = wr * 64 + mt * 16 + (lane & 15);
                uint32_t addr = As_u + arow * (AH_STRIDE * 2)
                              + ks * 32 + ((lane >> 4) * 16);
                asm volatile(
                    "ldmatrix.sync.aligned.m8n8.x4.shared.b16 {%0,%1,%2,%3}, [%4];"
                    : "=r"(a[mt][0]), "=r"(a[mt][1]),
                      "=r"(a[mt][2]), "=r"(a[mt][3])
                    : "r"(addr));
            }
            #pragma unroll
            for (int nt = 0; nt < 4; nt++) {
                int brow = ks * 16 + (lane & 15);
                uint32_t addr = Bs_u + brow * (BH_STRIDE * 2)
                              + (wc * 32 + nt * 8) * 2;
                asm volatile(
                    "ldmatrix.sync.aligned.m8n8.x2.trans.shared.b16 {%0,%1}, [%2];"
                    : "=r"(b[nt][0]), "=r"(b[nt][1])
                    : "r"(addr));
            }
            #pragma unroll
            for (int mt = 0; mt < 4; mt++)
                #pragma unroll
                for (int nt = 0; nt < 4; nt++) {
                    asm volatile(
                        "mma.sync.aligned.m16n8k16.row.col.f32.f16.f16.f32 "
                        "{%0,%1,%2,%3}, {%4,%5,%6,%7}, {%8,%9}, {%0,%1,%2,%3};"
                        : "+f"(acc[mt][nt][0]), "+f"(acc[mt][nt][1]),
                          "+f"(acc[mt][nt][2]), "+f"(acc[mt][nt][3])
                        : "r"(a[mt][0]), "r"(a[mt][1]),
                          "r"(a[mt][2]), "r"(a[mt][3]),
                          "r"(b[nt][0]), "r"(b[nt][1]));
                }
        }

        #pragma unroll
        for (int mt = 0; mt < 4; mt++) {
            int row = tile_row0 + wr * 64 + mt * 16 + g;
            #pragma unroll
            for (int nt = 0; nt < 4; nt++) {
                int col = wc * 32 + nt * 8 + 2 * tg;
                hj[(size_t)row * (OUT_C / 2) + col / 2] =
                    __floats2half2_rn(acc[mt][nt][0], acc[mt][nt][1]);
                hj[(size_t)(row + 8) * (OUT_C / 2) + col / 2] =
                    __floats2half2_rn(acc[mt][nt][2], acc[mt][nt][3]);
            }
        }
    }
}

// ---------------------------------------------------------------------------
// CSR build: count (x4, stores rank) -> scan_a -> scan_c -> fill (atomic-free)
// ---------------------------------------------------------------------------
#define E4 (N_EDGES / 4)   // 150000

__global__ void count_kernel(const int* __restrict__ d0,
                             const int* __restrict__ d1,
                             const int* __restrict__ d2) {
    unsigned gid = blockIdx.x * blockDim.x + threadIdx.x;
    if (gid >= 3u * E4) return;
    int rel = gid / E4;
    int e4  = gid % E4;
    const int* dp = (rel == 0) ? d0 : (rel == 1 ? d1 : d2);
    int4 d = __ldg(reinterpret_cast<const int4*>(dp) + e4);
    int4 r;
    r.x = atomicAdd(g_cnt + d.x, 1);
    r.y = atomicAdd(g_cnt + d.y, 1);
    r.z = atomicAdd(g_cnt + d.z, 1);
    r.w = atomicAdd(g_cnt + d.w, 1);
    reinterpret_cast<int4*>(g_rank)[rel * E4 + e4] = r;   // coalesced
}

__global__ void scan_a_kernel() {
    __shared__ int sb[256];
    int t = threadIdx.x;
    int base = blockIdx.x * SCAN_BS + t * 8;
    int sum = 0;
    #pragma unroll
    for (int j = 0; j < 8; j++) {
        int idx = base + j;
        if (idx < NB) sum += g_cnt[idx];
    }
    sb[t] = sum;
    __syncthreads();
    for (int off = 128; off > 0; off >>= 1) {
        if (t < off) sb[t] += sb[t + off];
        __syncthreads();
    }
    if (t == 0) g_partial[blockIdx.x] = sb[0];
}

__global__ void scan_c_kernel() {
    __shared__ int sb[256];
    __shared__ int base_sh;
    int t = threadIdx.x;

    int p = (t < (int)blockIdx.x && t < SCAN_BLOCKS) ? g_partial[t] : 0;
    sb[t] = p;
    __syncthreads();
    for (int off = 128; off > 0; off >>= 1) {
        if (t < off) sb[t] += sb[t + off];
        __syncthreads();
    }
    if (t == 0) base_sh = sb[0];
    __syncthreads();

    int base = blockIdx.x * SCAN_BS + t * 8;
    int v[8];
    int tsum = 0;
    #pragma unroll
    for (int j = 0; j < 8; j++) {
        int idx = base + j;
        v[j] = (idx < NB) ? g_cnt[idx] : 0;
        if (idx < NB) g_cnt[idx] = 0;          // re-zero for next run
        tsum += v[j];
    }
    sb[t] = tsum;
    __syncthreads();
    for (int off = 1; off < 256; off <<= 1) {
        int add = (t >= off) ? sb[t - off] : 0;
        __syncthreads();
        sb[t] += add;
        __syncthreads();
    }
    int run = base_sh + sb[t] - tsum;
    #pragma unroll
    for (int j = 0; j < 8; j++) {
        int idx = base + j;
        if (idx < NB) {
            g_rowstart[idx] = run;
            run += v[j];
        }
    }
    if (blockIdx.x == 0 && t == 0) g_rowstart[NB] = 3 * N_EDGES;
}

// atomic-free fill: pos = rowstart[dst] + rank (rank captured during count)
__global__ void fill_kernel(const int* __restrict__ s0, const int* __restrict__ d0,
                            const int* __restrict__ s1, const int* __restrict__ d1,
                            const int* __restrict__ s2, const int* __restrict__ d2) {
    unsigned gid = blockIdx.x * blockDim.x + threadIdx.x;
    if (gid >= 3u * E4) return;
    int rel = gid / E4;
    int e4  = gid % E4;
    const int* sp = (rel == 0) ? s0 : (rel == 1 ? s1 : s2);
    const int* dp = (rel == 0) ? d0 : (rel == 1 ? d1 : d2);
    int4 s = __ldg(reinterpret_cast<const int4*>(sp) + e4);
    int4 d = __ldg(reinterpret_cast<const int4*>(dp) + e4);
    int4 r = reinterpret_cast<const int4*>(g_rank)[rel * E4 + e4];
    // 4 independent L2 loads of rowstart (no atomics, no serialization)
    int b0 = __ldg(&g_rowstart[d.x]);
    int b1 = __ldg(&g_rowstart[d.y]);
    int b2 = __ldg(&g_rowstart[d.z]);
    int b3 = __ldg(&g_rowstart[d.w]);
    int rbase = rel * M_PAD;
    g_sorted[b0 + r.x] = rbase + s.x;
    g_sorted[b1 + r.y] = rbase + s.y;
    g_sorted[b2 + r.z] = rbase + s.z;
    g_sorted[b3 + r.w] = rbase + s.w;
}

// ---------------------------------------------------------------------------
// Gather: one warp per node, one flat segment, 8-wide unroll (unchanged)
// ---------------------------------------------------------------------------
__global__ void gather_kernel(float4* __restrict__ out4) {
    unsigned n    = (blockIdx.x * blockDim.x + threadIdx.x) >> 5;
    int      lane = threadIdx.x & 31;
    if (n >= (unsigned)N_NODES) return;

    int e   = __ldg(&g_rowstart[n]);
    int end = __ldg(&g_rowstart[n + 1]);

    const char* hb = reinterpret_cast<const char*>(g_hh);
    float4 acc = make_float4(0.f, 0.f, 0.f, 0.f);

    for (; e + 7 < end; e += 8) {
        int r[8];
        #pragma unroll
        for (int j = 0; j < 8; j++) r[j] = __ldg(&g_sorted[e + j]);
        uint2 u[8];
        #pragma unroll
        for (int j = 0; j < 8; j++)
            u[j] = __ldg(reinterpret_cast<const uint2*>(
                         hb + (size_t)r[j] * 256 + lane * 8));
        #pragma unroll
        for (int j = 0; j < 8; j++) {
            float2 f0 = __half22float2(*reinterpret_cast<__half2*>(&u[j].x));
            float2 f1 = __half22float2(*reinterpret_cast<__half2*>(&u[j].y));
            acc.x += f0.x; acc.y += f0.y; acc.z += f1.x; acc.w += f1.y;
        }
    }
    for (; e + 1 < end; e += 2) {
        int r0 = __ldg(&g_sorted[e]);
        int r1 = __ldg(&g_sorted[e + 1]);
        uint2 u0 = __ldg(reinterpret_cast<const uint2*>(hb + (size_t)r0 * 256 + lane * 8));
        uint2 u1 = __ldg(reinterpret_cast<const uint2*>(hb + (size_t)r1 * 256 + lane * 8));
        float2 a0 = __half22float2(*reinterpret_cast<__half2*>(&u0.x));
        float2 a1 = __half22float2(*reinterpret_cast<__half2*>(&u0.y));
        float2 b0 = __half22float2(*reinterpret_cast<__half2*>(&u1.x));
        float2 b1 = __half22float2(*reinterpret_cast<__half2*>(&u1.y));
        acc.x += a0.x + b0.x; acc.y += a0.y + b0.y;
        acc.z += a1.x + b1.x; acc.w += a1.y + b1.y;
    }
    if (e < end) {
        int r0 = __ldg(&g_sorted[e]);
        uint2 u = __ldg(reinterpret_cast<const uint2*>(hb + (size_t)r0 * 256 + lane * 8));
        float2 f0 = __half22float2(*reinterpret_cast<__half2*>(&u.x));
        float2 f1 = __half22float2(*reinterpret_cast<__half2*>(&u.y));
        acc.x += f0.x; acc.y += f0.y; acc.z += f1.x; acc.w += f1.y;
    }

    acc.x = fmaxf(acc.x, 0.f); acc.y = fmaxf(acc.y, 0.f);
    acc.z = fmaxf(acc.z, 0.f); acc.w = fmaxf(acc.w, 0.f);
    out4[(size_t)n * (OUT_C / 4) + lane] = acc;
}

// ---------------------------------------------------------------------------
// launch: CSR on side stream || GEMM on main stream, join, gather.
// ---------------------------------------------------------------------------
extern "C" void kernel_launch(void* const* d_in, const int* in_sizes, int n_in,
                              void* d_out, int out_size) {
    const float* x  = (const float*)d_in[0];
    const float* W0 = (const float*)d_in[1];
    const float* W1 = (const float*)d_in[2];
    const float* W2 = (const float*)d_in[3];
    const int* s0 = (const int*)d_in[4];
    const int* d0 = (const int*)d_in[5];
    const int* s1 = (const int*)d_in[6];
    const int* d1 = (const int*)d_in[7];
    const int* s2 = (const int*)d_in[8];
    const int* d2 = (const int*)d_in[9];
    float* out = (float*)d_out;

    static cudaStream_t s_side = nullptr;
    static cudaEvent_t  ev_fork = nullptr, ev_join = nullptr;
    static bool init_done = false;
    if (!init_done) {
        cudaStreamCreateWithFlags(&s_side, cudaStreamNonBlocking);
        cudaEventCreateWithFlags(&ev_fork, cudaEventDisableTiming);
        cudaEventCreateWithFlags(&ev_join, cudaEventDisableTiming);
        cudaFuncSetAttribute(gemm_hmma_kernel,
                             cudaFuncAttributeMaxDynamicSharedMemorySize,
                             SMEM_BYTES);
        init_done = true;
    }

    cudaEventRecord(ev_fork, 0);
    cudaStreamWaitEvent(s_side, ev_fork, 0);

    count_kernel<<<(3 * E4 + 255) / 256, 256, 0, s_side>>>(d0, d1, d2);
    scan_a_kernel<<<SCAN_BLOCKS, 256, 0, s_side>>>();
    scan_c_kernel<<<SCAN_BLOCKS, 256, 0, s_side>>>();
    fill_kernel<<<(3 * E4 + 255) / 256, 256, 0, s_side>>>(s0, d0, s1, d1, s2, d2);
    cudaEventRecord(ev_join, s_side);

    gemm_hmma_kernel<<<N_TILES, 256, SMEM_BYTES>>>(
        reinterpret_cast<const float4*>(x), W0, W1, W2);

    cudaStreamWaitEvent(0, ev_join, 0);
    {
        long long threads = (long long)N_NODES * 32;
        int blocks = (int)((threads + 255) / 256);
        gather_kernel<<<blocks, 256>>>(reinterpret_cast<float4*>(out));
    }
}